// round 6
// baseline (speedup 1.0000x reference)
#include <cuda_runtime.h>

// Problem constants
#define B_   32
#define T_   16384
#define H_   64
#define NTHR 128          // 4 warps: thread = (unit, K-half)

typedef unsigned long long u64;

// ---- packed f32x2 helpers ----
__device__ __forceinline__ u64 pack2(float lo, float hi) {
    u64 r; asm("mov.b64 %0, {%1, %2};" : "=l"(r) : "f"(lo), "f"(hi)); return r;
}
__device__ __forceinline__ void unpack2(u64 v, float& lo, float& hi) {
    asm("mov.b64 {%0, %1}, %2;" : "=f"(lo), "=f"(hi) : "l"(v));
}
__device__ __forceinline__ void fma2(u64& d, u64 a, u64 b) {
    asm("fma.rn.f32x2 %0, %1, %2, %0;" : "+l"(d) : "l"(a), "l"(b));
}
__device__ __forceinline__ void add2(u64& d, u64 a) {
    asm("add.rn.f32x2 %0, %0, %1;" : "+l"(d) : "l"(a));
}
__device__ __forceinline__ float tanhhw(float v) {      // MUFU.TANH, lat 16
    float r; asm("tanh.approx.f32 %0, %1;" : "=f"(r) : "f"(v)); return r;
}

// ============================================================================
// Recurrence: one CTA (128 threads) per batch element.
//   unit = wid*16 + (lane&15), half = lane>>4 (K-half of the dots)
// sigma(v) = 0.5 + 0.5*tanh(v/2); all three gates via MUFU.TANH.
// Serial tail minimized:
//   n-dot accumulator initialized with b_hh_n (half 0 only)
//   q  = 0.5*(1+tr)                (off critical path)
//   vn = fmaf(q, dp, fmaf(q, ds, inp))   -> post-shfl chain = 1 FMA + TANH
//   Ah = A*h precomputed            -> post-tanh chain = 1 FMA + STS
// x consumed as float4 per 4 steps, prefetched one group ahead.
// ============================================================================
__global__ __launch_bounds__(NTHR, 1) void gru_scan_kernel(
    const float* __restrict__ x,      // [B,T,1]
    const float* __restrict__ w_ih,   // [192,1]
    const float* __restrict__ w_hh,   // [192,64]
    const float* __restrict__ b_ih,   // [192]
    const float* __restrict__ b_hh,   // [192]
    float* __restrict__ states)       // [B,T,64]
{
    __shared__ __align__(16) float hbuf[2][H_];

    const int tid  = threadIdx.x;
    const int wid  = tid >> 5;
    const int lane = tid & 31;
    const int unit = wid * 16 + (lane & 15);
    const int half = lane >> 4;
    const int b    = blockIdx.x;

    // ---- register-resident weights: rows unit, 64+unit, 128+unit; K-half ----
    u64 wr[16], wz[16], wn[16];
    {
        const float4* pr = reinterpret_cast<const float4*>(w_hh + (unit        ) * H_ + half * 32);
        const float4* pz = reinterpret_cast<const float4*>(w_hh + (unit +   H_ ) * H_ + half * 32);
        const float4* pn = reinterpret_cast<const float4*>(w_hh + (unit + 2*H_ ) * H_ + half * 32);
        #pragma unroll
        for (int i = 0; i < 8; i++) {
            float4 a = pr[i]; wr[2*i] = pack2(a.x, a.y); wr[2*i+1] = pack2(a.z, a.w);
            float4 c = pz[i]; wz[2*i] = pack2(c.x, c.y); wz[2*i+1] = pack2(c.z, c.w);
            float4 d = pn[i]; wn[2*i] = pack2(d.x, d.y); wn[2*i+1] = pack2(d.z, d.w);
        }
    }

    // ---- per-unit scalar constants ----
    const float wirh  = 0.5f * w_ih[unit];             // 0.5*w_ih_r
    const float wizh  = 0.5f * w_ih[H_ + unit];        // 0.5*w_ih_z
    const float win   =        w_ih[2*H_ + unit];      // w_ih_n
    const float crh   = 0.5f * (b_ih[unit]      + b_hh[unit]);
    const float czh   = 0.5f * (b_ih[H_ + unit] + b_hh[H_ + unit]);
    const float bin   =        b_ih[2*H_ + unit];
    const float nacc0 = half ? 0.0f : b_hh[2*H_ + unit];  // fold b_hh_n into ds

    if (tid < H_) hbuf[0][tid] = 0.0f;   // h0 = 0
    __syncthreads();

    const float* xb  = x + (size_t)b * T_;
    float*       stp = states + (size_t)b * T_ * H_ + unit;

    float h_reg = 0.0f;     // this unit's h (tracked identically in both halves)

#define STEP(XC, P, STOFF)                                                     \
    do {                                                                       \
        const ulonglong2* hp =                                                 \
            reinterpret_cast<const ulonglong2*>(&hbuf[P][half * 32]);          \
        u64 h2[16];                                                            \
        _Pragma("unroll")                                                      \
        for (int i = 0; i < 8; i++) {                                          \
            ulonglong2 v = hp[i]; h2[2*i] = v.x; h2[2*i+1] = v.y;              \
        }                                                                      \
        const float pre_r = fmaf((XC), wirh, crh);                             \
        const float pre_z = fmaf((XC), wizh, czh);                             \
        const float inp   = fmaf((XC), win,  bin);                             \
        /* r-dot */                                                            \
        u64 ar0 = pack2(0.f, 0.f), ar1 = pack2(0.f, 0.f);                      \
        _Pragma("unroll")                                                      \
        for (int i = 0; i < 16; i += 2) {                                      \
            fma2(ar0, h2[i], wr[i]);  fma2(ar1, h2[i+1], wr[i+1]);             \
        }                                                                      \
        add2(ar0, ar1);                                                        \
        float rl, rh_; unpack2(ar0, rl, rh_);                                  \
        float drs = rl + rh_;                                                  \
        float drp = __shfl_xor_sync(0xFFFFFFFFu, drs, 16);                     \
        float tr  = tanhhw(fmaf(0.5f, drp, fmaf(0.5f, drs, pre_r)));           \
        float q   = fmaf(0.5f, tr, 0.5f);          /* 0.5*(1+tr), off-path */  \
        /* z-dot */                                                            \
        u64 az0 = pack2(0.f, 0.f), az1 = pack2(0.f, 0.f);                      \
        _Pragma("unroll")                                                      \
        for (int i = 0; i < 16; i += 2) {                                      \
            fma2(az0, h2[i], wz[i]);  fma2(az1, h2[i+1], wz[i+1]);             \
        }                                                                      \
        add2(az0, az1);                                                        \
        float zl, zh_; unpack2(az0, zl, zh_);                                  \
        float dzs = zl + zh_;                                                  \
        float dzp = __shfl_xor_sync(0xFFFFFFFFu, dzs, 16);                     \
        float tz  = tanhhw(fmaf(0.5f, dzp, fmaf(0.5f, dzs, pre_z)));           \
        float A   = fmaf(tz,  0.25f, 0.75f);                                   \
        float BB  = fmaf(tz, -0.25f, 0.25f);                                   \
        float Ah  = A * h_reg;                      /* off-path */             \
        /* n-dot (accumulator carries b_hh_n via nacc0 in half 0) */           \
        u64 an0 = pack2(nacc0, 0.f), an1 = pack2(0.f, 0.f);                    \
        _Pragma("unroll")                                                      \
        for (int i = 0; i < 16; i += 2) {                                      \
            fma2(an0, h2[i], wn[i]);  fma2(an1, h2[i+1], wn[i+1]);             \
        }                                                                      \
        add2(an0, an1);                                                        \
        float nl, nh_; unpack2(an0, nl, nh_);                                  \
        float ds   = nl + nh_;                                                 \
        float dp   = __shfl_xor_sync(0xFFFFFFFFu, ds, 16);                     \
        float base = fmaf(q, ds, inp);              /* overlaps the shfl */    \
        float n    = tanhhw(fmaf(q, dp, base));                                \
        float hnew = fmaf(BB, n, Ah);                                          \
        h_reg = hnew;                                                          \
        if (half == 0) {                                                       \
            hbuf[(P) ^ 1][unit] = hnew;                                        \
            stp[(STOFF) * H_]   = hnew;                                        \
        }                                                                      \
        __syncthreads();                                                       \
    } while (0)

    float4 xq = *reinterpret_cast<const float4*>(xb);
    for (int tg = 0; tg < T_; tg += 4) {
        // prefetch next group's x (wraps harmlessly to group 0 at the end)
        float4 xq_n = *reinterpret_cast<const float4*>(xb + ((tg + 4) & (T_ - 1)));
        STEP(xq.x, 0, 0);
        STEP(xq.y, 1, 1);
        STEP(xq.z, 0, 2);
        STEP(xq.w, 1, 3);
        stp += 4 * H_;
        xq = xq_n;
    }
#undef STEP
}

// ============================================================================
// Output projection: out[b,t] = states[b,t,:] . w_out + b_out + x[b,t]
// 2 rows per warp per iteration, float4 loads (512B/warp), 4-deep reduce.
// ============================================================================
__global__ __launch_bounds__(256) void out_proj_kernel(
    const float* __restrict__ states,  // [B*T, 64]
    const float* __restrict__ x,       // [B*T]
    const float* __restrict__ w_out,   // [64]
    const float* __restrict__ b_out,   // [1]
    float* __restrict__ out)           // [B*T]
{
    const int lane  = threadIdx.x & 31;
    const int sub   = lane & 15;       // position within row
    const int hr    = lane >> 4;       // which of the 2 rows
    const int warp  = (blockIdx.x * blockDim.x + threadIdx.x) >> 5;
    const int nwarp = (gridDim.x * blockDim.x) >> 5;

    const float4 w = reinterpret_cast<const float4*>(w_out)[sub];
    const float bo = b_out[0];

    const int npairs = (B_ * T_) >> 1;
    for (int pair = warp; pair < npairs; pair += nwarp) {
        const int row = 2 * pair + hr;
        const float4 s = reinterpret_cast<const float4*>(states + (size_t)row * H_)[sub];
        float v = fmaf(s.x, w.x, fmaf(s.y, w.y, fmaf(s.z, w.z, s.w * w.w)));
        #pragma unroll
        for (int o = 8; o > 0; o >>= 1)
            v += __shfl_xor_sync(0xFFFFFFFFu, v, o);
        if (sub == 0) out[row] = v + bo + x[row];
    }
}

// ============================================================================
// Launch: d_out = [ out (B*T floats) | states (B*T*H floats) ]
// ============================================================================
extern "C" void kernel_launch(void* const* d_in, const int* in_sizes, int n_in,
                              void* d_out, int out_size)
{
    const float* x     = (const float*)d_in[0];
    const float* w_ih  = (const float*)d_in[1];
    const float* w_hh  = (const float*)d_in[2];
    const float* b_ih  = (const float*)d_in[3];
    const float* b_hh  = (const float*)d_in[4];
    const float* w_out = (const float*)d_in[5];
    const float* b_out = (const float*)d_in[6];

    float* out    = (float*)d_out;
    float* states = out + (size_t)B_ * T_;

    gru_scan_kernel<<<B_, NTHR>>>(x, w_ih, w_hh, b_ih, b_hh, states);
    out_proj_kernel<<<1184, 256>>>(states, x, w_out, b_out, out);
}

// round 7
// speedup vs baseline: 1.0020x; 1.0020x over previous
#include <cuda_runtime.h>

// Problem constants
#define B_   32
#define T_   16384
#define H_   64
#define NTHR 128          // 4 warps: thread = (unit, K-half)

typedef unsigned long long u64;

// ---- packed f32x2 helpers ----
__device__ __forceinline__ u64 pack2(float lo, float hi) {
    u64 r; asm("mov.b64 %0, {%1, %2};" : "=l"(r) : "f"(lo), "f"(hi)); return r;
}
__device__ __forceinline__ void unpack2(u64 v, float& lo, float& hi) {
    asm("mov.b64 {%0, %1}, %2;" : "=f"(lo), "=f"(hi) : "l"(v));
}
__device__ __forceinline__ void fma2(u64& d, u64 a, u64 b) {
    asm("fma.rn.f32x2 %0, %1, %2, %0;" : "+l"(d) : "l"(a), "l"(b));
}
__device__ __forceinline__ void add2(u64& d, u64 a) {
    asm("add.rn.f32x2 %0, %0, %1;" : "+l"(d) : "l"(a));
}
__device__ __forceinline__ float tanhhw(float v) {      // MUFU.TANH, lat 16
    float r; asm("tanh.approx.f32 %0, %1;" : "=f"(r) : "f"(v)); return r;
}

// ============================================================================
// Recurrence: one CTA (128 threads) per batch element.
//   unit = wid*16 + (lane&15), half = lane>>4 (K-half of the dots)
// sigma(v) = 0.5 + 0.5*tanh(v/2); all three gates via MUFU.TANH.
// Serial tail minimized:
//   n-dot accumulator initialized with b_hh_n (half 0 only)
//   q  = 0.5*(1+tr)                (off critical path)
//   vn = fmaf(q, dp, fmaf(q, ds, inp))   -> post-shfl chain = 1 FMA + TANH
//   Ah = A*h precomputed            -> post-tanh chain = 1 FMA + STS
// x consumed as float4 per 4 steps, prefetched one group ahead.
// ============================================================================
__global__ __launch_bounds__(NTHR, 1) void gru_scan_kernel(
    const float* __restrict__ x,      // [B,T,1]
    const float* __restrict__ w_ih,   // [192,1]
    const float* __restrict__ w_hh,   // [192,64]
    const float* __restrict__ b_ih,   // [192]
    const float* __restrict__ b_hh,   // [192]
    float* __restrict__ states)       // [B,T,64]
{
    __shared__ __align__(16) float hbuf[2][H_];

    const int tid  = threadIdx.x;
    const int wid  = tid >> 5;
    const int lane = tid & 31;
    const int unit = wid * 16 + (lane & 15);
    const int half = lane >> 4;
    const int b    = blockIdx.x;

    // ---- register-resident weights: rows unit, 64+unit, 128+unit; K-half ----
    u64 wr[16], wz[16], wn[16];
    {
        const float4* pr = reinterpret_cast<const float4*>(w_hh + (unit        ) * H_ + half * 32);
        const float4* pz = reinterpret_cast<const float4*>(w_hh + (unit +   H_ ) * H_ + half * 32);
        const float4* pn = reinterpret_cast<const float4*>(w_hh + (unit + 2*H_ ) * H_ + half * 32);
        #pragma unroll
        for (int i = 0; i < 8; i++) {
            float4 a = pr[i]; wr[2*i] = pack2(a.x, a.y); wr[2*i+1] = pack2(a.z, a.w);
            float4 c = pz[i]; wz[2*i] = pack2(c.x, c.y); wz[2*i+1] = pack2(c.z, c.w);
            float4 d = pn[i]; wn[2*i] = pack2(d.x, d.y); wn[2*i+1] = pack2(d.z, d.w);
        }
    }

    // ---- per-unit scalar constants ----
    const float wirh  = 0.5f * w_ih[unit];             // 0.5*w_ih_r
    const float wizh  = 0.5f * w_ih[H_ + unit];        // 0.5*w_ih_z
    const float win   =        w_ih[2*H_ + unit];      // w_ih_n
    const float crh   = 0.5f * (b_ih[unit]      + b_hh[unit]);
    const float czh   = 0.5f * (b_ih[H_ + unit] + b_hh[H_ + unit]);
    const float bin   =        b_ih[2*H_ + unit];
    const float nacc0 = half ? 0.0f : b_hh[2*H_ + unit];  // fold b_hh_n into ds

    if (tid < H_) hbuf[0][tid] = 0.0f;   // h0 = 0
    __syncthreads();

    const float* xb  = x + (size_t)b * T_;
    float*       stp = states + (size_t)b * T_ * H_ + unit;

    float h_reg = 0.0f;     // this unit's h (tracked identically in both halves)

#define STEP(XC, P, STOFF)                                                     \
    do {                                                                       \
        const ulonglong2* hp =                                                 \
            reinterpret_cast<const ulonglong2*>(&hbuf[P][half * 32]);          \
        u64 h2[16];                                                            \
        _Pragma("unroll")                                                      \
        for (int i = 0; i < 8; i++) {                                          \
            ulonglong2 v = hp[i]; h2[2*i] = v.x; h2[2*i+1] = v.y;              \
        }                                                                      \
        const float pre_r = fmaf((XC), wirh, crh);                             \
        const float pre_z = fmaf((XC), wizh, czh);                             \
        const float inp   = fmaf((XC), win,  bin);                             \
        /* r-dot */                                                            \
        u64 ar0 = pack2(0.f, 0.f), ar1 = pack2(0.f, 0.f);                      \
        _Pragma("unroll")                                                      \
        for (int i = 0; i < 16; i += 2) {                                      \
            fma2(ar0, h2[i], wr[i]);  fma2(ar1, h2[i+1], wr[i+1]);             \
        }                                                                      \
        add2(ar0, ar1);                                                        \
        float rl, rh_; unpack2(ar0, rl, rh_);                                  \
        float drs = rl + rh_;                                                  \
        float drp = __shfl_xor_sync(0xFFFFFFFFu, drs, 16);                     \
        float tr  = tanhhw(fmaf(0.5f, drp, fmaf(0.5f, drs, pre_r)));           \
        float q   = fmaf(0.5f, tr, 0.5f);          /* 0.5*(1+tr), off-path */  \
        /* z-dot */                                                            \
        u64 az0 = pack2(0.f, 0.f), az1 = pack2(0.f, 0.f);                      \
        _Pragma("unroll")                                                      \
        for (int i = 0; i < 16; i += 2) {                                      \
            fma2(az0, h2[i], wz[i]);  fma2(az1, h2[i+1], wz[i+1]);             \
        }                                                                      \
        add2(az0, az1);                                                        \
        float zl, zh_; unpack2(az0, zl, zh_);                                  \
        float dzs = zl + zh_;                                                  \
        float dzp = __shfl_xor_sync(0xFFFFFFFFu, dzs, 16);                     \
        float tz  = tanhhw(fmaf(0.5f, dzp, fmaf(0.5f, dzs, pre_z)));           \
        float A   = fmaf(tz,  0.25f, 0.75f);                                   \
        float BB  = fmaf(tz, -0.25f, 0.25f);                                   \
        float Ah  = A * h_reg;                      /* off-path */             \
        /* n-dot (accumulator carries b_hh_n via nacc0 in half 0) */           \
        u64 an0 = pack2(nacc0, 0.f), an1 = pack2(0.f, 0.f);                    \
        _Pragma("unroll")                                                      \
        for (int i = 0; i < 16; i += 2) {                                      \
            fma2(an0, h2[i], wn[i]);  fma2(an1, h2[i+1], wn[i+1]);             \
        }                                                                      \
        add2(an0, an1);                                                        \
        float nl, nh_; unpack2(an0, nl, nh_);                                  \
        float ds   = nl + nh_;                                                 \
        float dp   = __shfl_xor_sync(0xFFFFFFFFu, ds, 16);                     \
        float base = fmaf(q, ds, inp);              /* overlaps the shfl */    \
        float n    = tanhhw(fmaf(q, dp, base));                                \
        float hnew = fmaf(BB, n, Ah);                                          \
        h_reg = hnew;                                                          \
        if (half == 0) {                                                       \
            hbuf[(P) ^ 1][unit] = hnew;                                        \
            stp[(STOFF) * H_]   = hnew;                                        \
        }                                                                      \
        __syncthreads();                                                       \
    } while (0)

    float4 xq = *reinterpret_cast<const float4*>(xb);
    for (int tg = 0; tg < T_; tg += 4) {
        // prefetch next group's x (wraps harmlessly to group 0 at the end)
        float4 xq_n = *reinterpret_cast<const float4*>(xb + ((tg + 4) & (T_ - 1)));
        STEP(xq.x, 0, 0);
        STEP(xq.y, 1, 1);
        STEP(xq.z, 0, 2);
        STEP(xq.w, 1, 3);
        stp += 4 * H_;
        xq = xq_n;
    }
#undef STEP
}

// ============================================================================
// Output projection: out[b,t] = states[b,t,:] . w_out + b_out + x[b,t]
// 2 rows per warp per iteration, float4 loads (512B/warp), 4-deep reduce.
// ============================================================================
__global__ __launch_bounds__(256) void out_proj_kernel(
    const float* __restrict__ states,  // [B*T, 64]
    const float* __restrict__ x,       // [B*T]
    const float* __restrict__ w_out,   // [64]
    const float* __restrict__ b_out,   // [1]
    float* __restrict__ out)           // [B*T]
{
    const int lane  = threadIdx.x & 31;
    const int sub   = lane & 15;       // position within row
    const int hr    = lane >> 4;       // which of the 2 rows
    const int warp  = (blockIdx.x * blockDim.x + threadIdx.x) >> 5;
    const int nwarp = (gridDim.x * blockDim.x) >> 5;

    const float4 w = reinterpret_cast<const float4*>(w_out)[sub];
    const float bo = b_out[0];

    const int npairs = (B_ * T_) >> 1;
    for (int pair = warp; pair < npairs; pair += nwarp) {
        const int row = 2 * pair + hr;
        const float4 s = reinterpret_cast<const float4*>(states + (size_t)row * H_)[sub];
        float v = fmaf(s.x, w.x, fmaf(s.y, w.y, fmaf(s.z, w.z, s.w * w.w)));
        #pragma unroll
        for (int o = 8; o > 0; o >>= 1)
            v += __shfl_xor_sync(0xFFFFFFFFu, v, o);
        if (sub == 0) out[row] = v + bo + x[row];
    }
}

// ============================================================================
// Launch: d_out = [ out (B*T floats) | states (B*T*H floats) ]
// ============================================================================
extern "C" void kernel_launch(void* const* d_in, const int* in_sizes, int n_in,
                              void* d_out, int out_size)
{
    const float* x     = (const float*)d_in[0];
    const float* w_ih  = (const float*)d_in[1];
    const float* w_hh  = (const float*)d_in[2];
    const float* b_ih  = (const float*)d_in[3];
    const float* b_hh  = (const float*)d_in[4];
    const float* w_out = (const float*)d_in[5];
    const float* b_out = (const float*)d_in[6];

    float* out    = (float*)d_out;
    float* states = out + (size_t)B_ * T_;

    gru_scan_kernel<<<B_, NTHR>>>(x, w_ih, w_hh, b_ih, b_hh, states);
    out_proj_kernel<<<1184, 256>>>(states, x, w_out, b_out, out);
}